// round 15
// baseline (speedup 1.0000x reference)
#include <cuda_runtime.h>
#include <math.h>

#define BB 4
#define LL 512
#define VV 32128
#define AVV 32000
#define DD 768
#define NT (BB*LL)
#define NV4 (VV/4)      // 8032
#define ND4 (DD/4)      // 192
#define NTH 256
#define CH 2            // chunks per token
#define CV4 (NV4/CH)    // 4016 float4 per chunk

#define NBLK_SCAN (NT*CH)
#define GRID_TOTAL (BB + NBLK_SCAN + NT)

// Scratch (device globals; no allocation allowed)
__device__ int4         g_part[NT * CH]; // per (token,chunk) top-2
__device__ unsigned int g_cnt[NT];       // produced-chunk counter (reset by consumer)
__device__ int          g_ps[NT];        // psg row (-1 = none)
__device__ unsigned int g_psflag[BB];    // set-once ready flags (replay-identical data)

// ---------------------------------------------------------------------------
// Exact coarse key: lo - log(-log u). Series path near u=1: winners have
// u ~ 1-3e-5 where __logf's ~1e-6 ABSOLUTE error would be catastrophic
// relative error on t = -log u. Abs key error bounded ~1.2e-4.
// ---------------------------------------------------------------------------
__device__ __forceinline__ float coarse_key(float lo, float u) {
    float w  = 1.0f - u;                 // exact for u > 0.5 (Sterbenz)
    float ts = fmaf(0.5f * w, w, w);     // w + w^2/2
    float tl = -__logf(u);
    float t  = (u > 0.99609375f) ? ts : tl;
    return lo - __logf(t);
}

__device__ __forceinline__ double precise_key(float lo, float u) {
    return (double)lo - log(-log((double)u));
}

__device__ __forceinline__ void ins2(float k, int j,
                                     float& v1, int& i1,
                                     float& v2, int& i2) {
    bool p = k > v1;
    float dv = p ? v1 : k;
    int   di = p ? i1 : j;
    if (p) { v1 = k; i1 = j; }
    if (dv > v2) { v2 = dv; i2 = di; }
}

__device__ __forceinline__ void top2_insert(float w, int j,
                                            float& v1, int& i1,
                                            float& v2, int& i2) {
    if (w > v1 || (w == v1 && j < i1)) {
        v2 = v1; i2 = i1; v1 = w; i1 = j;
    } else if (w > v2 || (w == v2 && j < i2)) {
        v2 = w; i2 = j;
    }
}

// ---------------------------------------------------------------------------
// ONE launch: [psg blocks BB] [scan blocks NT*CH] [finish blocks NT].
// CTAs dispatch in ID order => all producers dispatched before consumers.
// __launch_bounds__(NTH, 8) caps regs at 32 (scan hot path fits; cold paths
// may spill — harmless).
// ---------------------------------------------------------------------------
__global__ void __launch_bounds__(NTH, 8)
fused_kernel(const float* __restrict__ logits,
             const float* __restrict__ gu,
             const float* __restrict__ W,
             const int*   __restrict__ rwrt,
             const int*   __restrict__ psg_in,
             float*       __restrict__ out) {
    const int tid = threadIdx.x;

    // ================= psg blocks =================
    if (blockIdx.x < BB) {
        __shared__ int s_r[LL];
        __shared__ int s_p[LL];
        const int b = blockIdx.x;
        if (tid >= 32) return;
        const int lane = tid;

        int cnt = 0;
#pragma unroll
        for (int k = 0; k < LL / 32; k++) {
            int l  = lane + 32 * k;
            int rv = rwrt[b * LL + l];
            s_r[l] = rv;
            s_p[l] = psg_in[b * LL + l];
            cnt += (rv == 1);
        }
        __syncwarp();
#pragma unroll
        for (int o = 16; o > 0; o >>= 1)
            cnt += __shfl_xor_sync(0xFFFFFFFFu, cnt, o);
        const int shift = cnt;

        int tr[LL / 32];
        int firstnz = LL;
#pragma unroll
        for (int k = 0; k < LL / 32; k++) {
            int l   = lane + 32 * k;
            int pos = ((l - shift) % LL + LL) % LL;
            int fm  = 1 - s_r[LL - 1 - pos];
            int psv = (pos == 0) ? 1 : s_p[pos - 1];
            int t   = fm * psv;
            tr[k] = t;
            if (t != 0) firstnz = min(firstnz, l);
        }
#pragma unroll
        for (int o = 16; o > 0; o >>= 1)
            firstnz = min(firstnz, __shfl_xor_sync(0xFFFFFFFFu, firstnz, o));
#pragma unroll
        for (int k = 0; k < LL / 32; k++) {
            int l = lane + 32 * k;
            g_ps[b * LL + l] = (l >= firstnz) ? tr[k] : -1;
        }
        __syncwarp();
        if (lane == 0) {
            __threadfence();
            g_psflag[b] = 1u;    // set-once; data identical on every replay
        }
        return;
    }

    // ================= finish blocks (grid tail) =================
    if (blockIdx.x >= BB + NBLK_SCAN) {
        const int t = blockIdx.x - (BB + NBLK_SCAN);   // 0..NT-1
        const int b = t / LL;
        __shared__ int s_res[2];

        if (tid == 0) {
            while (__ldcg(&g_cnt[t]) < (unsigned)CH) __nanosleep(64);
            while (__ldcg(&g_psflag[b]) == 0u)       __nanosleep(64);
            __threadfence();   // acquire
        }
        __syncthreads();

        if (tid < 32) {
            float v1 = -INFINITY, v2 = -INFINITY;
            int   i1 = 0,         i2 = 1;
            if (tid < CH) {
                int4 pr = __ldcg((int4*)&g_part[t * CH + tid]);
                v1 = __int_as_float(pr.x); i1 = pr.y;
                v2 = __int_as_float(pr.z); i2 = pr.w;
            }
#pragma unroll
            for (int off = 4; off > 0; off >>= 1) {
                float w1 = __shfl_xor_sync(0xFFFFFFFFu, v1, off);
                int   j1 = __shfl_xor_sync(0xFFFFFFFFu, i1, off);
                float w2 = __shfl_xor_sync(0xFFFFFFFFu, v2, off);
                int   j2 = __shfl_xor_sync(0xFFFFFFFFu, i2, off);
                top2_insert(w1, j1, v1, i1, v2, i2);
                top2_insert(w2, j2, v1, i1, v2, i2);
            }
            if (tid == 0) {
                int win = i1;
                if (v1 - v2 < 4e-3f) {
                    // near-tie (~0.4%): fp64 re-decide; coarse error <= 2.4e-4
                    double k1 = precise_key(logits[(size_t)t * VV + i1],
                                            gu[(size_t)t * VV + i1]);
                    double k2 = precise_key(logits[(size_t)t * VV + i2],
                                            gu[(size_t)t * VV + i2]);
                    if (k2 > k1 || (k2 == k1 && i2 < i1)) win = i2;
                }
                s_res[0] = (rwrt[t] != 0 && win < AVV) ? win : -1;
                s_res[1] = g_ps[t];
                g_cnt[t] = 0u;     // reset for next graph replay (sole consumer)
            }
        }
        __syncthreads();

        if (tid < ND4) {
            const int am = s_res[0];
            const int ps = s_res[1];
            const float4* W4 = (const float4*)W;
            float4 acc = make_float4(0.f, 0.f, 0.f, 0.f);
            if (am >= 0) acc = W4[(size_t)am * ND4 + tid];
            if (ps >= 0) {
                float4 wv = W4[(size_t)ps * ND4 + tid];
                acc.x += wv.x; acc.y += wv.y; acc.z += wv.z; acc.w += wv.w;
            }
            ((float4*)out)[(size_t)t * ND4 + tid] = acc;
        }
        return;
    }

    // ================= scan blocks (R13 hot loop, CH=2) =================
    const int blk = blockIdx.x - BB;
    const int t   = blk >> 1;
    const int c   = blk & 1;

    const float4* lg = (const float4*)(logits + (size_t)t * VV) + c * CV4;
    const float4* gg = (const float4*)(gu     + (size_t)t * VV) + c * CV4;
    const int jbase = c * CV4 * 4;

    float v1 = -INFINITY, v2 = -INFINITY;
    int   i1 = 0,         i2 = 1;

    // seed: one exact float4 per lane, warp-wide 2nd-max -> thr
    {
        float4 a = __ldcs(lg + tid);
        float4 g = __ldcs(gg + tid);
        int base = jbase + 4 * tid;
        ins2(coarse_key(a.x, g.x), base + 0, v1, i1, v2, i2);
        ins2(coarse_key(a.y, g.y), base + 1, v1, i1, v2, i2);
        ins2(coarse_key(a.z, g.z), base + 2, v1, i1, v2, i2);
        ins2(coarse_key(a.w, g.w), base + 3, v1, i1, v2, i2);
    }
    float sa = v1, sb = v2;
#pragma unroll
    for (int off = 16; off > 0; off >>= 1) {
        float oa = __shfl_xor_sync(0xFFFFFFFFu, sa, off);
        float ob = __shfl_xor_sync(0xFFFFFFFFu, sb, off);
        float hi  = fmaxf(sa, oa);
        float lo2 = fmaxf(fminf(sa, oa), fmaxf(sb, ob));
        sa = hi; sb = lo2;
    }

    const float CC  = 8.2629582e-8f;    // ln2 / 2^23
    const float CBE = 88.029703f;       // 127*ln2 + 1e-5 margin
    float thr2 = fmaxf(v2, sb) - CBE;

#pragma unroll 2
    for (int i = tid + NTH; i < CV4; i += NTH) {
        float4 a = __ldcs(lg + i);
        float4 g = __ldcs(gg + i);
        float ub0 = fmaf(-CC, (float)__float_as_int(1.0f - g.x), a.x);
        float ub1 = fmaf(-CC, (float)__float_as_int(1.0f - g.y), a.y);
        float ub2 = fmaf(-CC, (float)__float_as_int(1.0f - g.z), a.z);
        float ub3 = fmaf(-CC, (float)__float_as_int(1.0f - g.w), a.w);
        float m = fmaxf(fmaxf(ub0, ub1), fmaxf(ub2, ub3));
        if (m > thr2) {
            int base = jbase + 4 * i;
            ins2(coarse_key(a.x, g.x), base + 0, v1, i1, v2, i2);
            ins2(coarse_key(a.y, g.y), base + 1, v1, i1, v2, i2);
            ins2(coarse_key(a.z, g.z), base + 2, v1, i1, v2, i2);
            ins2(coarse_key(a.w, g.w), base + 3, v1, i1, v2, i2);
            thr2 = fmaxf(thr2, v2 - CBE);
        }
    }

    // block top-2 reduction (index tie-break)
    __shared__ float s_v1[NTH]; __shared__ int s_i1[NTH];
    __shared__ float s_v2[NTH]; __shared__ int s_i2[NTH];
    s_v1[tid] = v1; s_i1[tid] = i1;
    s_v2[tid] = v2; s_i2[tid] = i2;
    __syncthreads();
    for (int s = NTH / 2; s > 0; s >>= 1) {
        if (tid < s) {
            float w1 = s_v1[tid + s], w2 = s_v2[tid + s];
            int   j1 = s_i1[tid + s], j2 = s_i2[tid + s];
            float a1 = s_v1[tid],     a2 = s_v2[tid];
            int   c1 = s_i1[tid],     c2 = s_i2[tid];
            top2_insert(w1, j1, a1, c1, a2, c2);
            top2_insert(w2, j2, a1, c1, a2, c2);
            s_v1[tid] = a1; s_i1[tid] = c1;
            s_v2[tid] = a2; s_i2[tid] = c2;
        }
        __syncthreads();
    }
    if (tid == 0) {
        g_part[blk] = make_int4(__float_as_int(s_v1[0]), s_i1[0],
                                __float_as_int(s_v2[0]), s_i2[0]);
        __threadfence();                       // release partial before count
        atomicAdd(&g_cnt[t], 1u);
    }
}

// ---------------------------------------------------------------------------
extern "C" void kernel_launch(void* const* d_in, const int* in_sizes, int n_in,
                              void* d_out, int out_size) {
    const float* logits = (const float*)d_in[0];
    const float* gu     = (const float*)d_in[1];
    const float* W      = (const float*)d_in[2];
    const int*   rwrt   = (const int*)d_in[3];
    const int*   psg    = (const int*)d_in[4];
    float* out = (float*)d_out;

    fused_kernel<<<GRID_TOTAL, NTH>>>(logits, gu, W, rwrt, psg, out);
}

// round 16
// speedup vs baseline: 1.2251x; 1.2251x over previous
#include <cuda_runtime.h>
#include <math.h>

#define BB 4
#define LL 512
#define VV 32128
#define AVV 32000
#define DD 768
#define NT (BB*LL)
#define NV4 (VV/4)      // 8032
#define ND4 (DD/4)      // 192
#define NTH 256
#define CH 4            // chunks per token
#define CV4 (NV4/CH)    // 2008 float4 per chunk

#define NBLK_SCAN (NT*CH)
#define GRID_TOTAL (BB + NBLK_SCAN + NT)

// Scratch (device globals; no allocation allowed)
__device__ int4         g_part[NT * CH]; // per (token,chunk) top-2
__device__ unsigned int g_cnt[NT];       // produced-chunk counter (reset by consumer)
__device__ int          g_ps[NT];        // psg row (-1 = none)
__device__ unsigned int g_psflag[BB];    // set-once ready flags (replay-identical data)

// ---------------------------------------------------------------------------
// Exact coarse key: lo - log(-log u). Series path near u=1: winners have
// u ~ 1-3e-5 where __logf's ~1e-6 ABSOLUTE error would be catastrophic
// relative error on t = -log u. Abs key error bounded ~1.2e-4.
// ---------------------------------------------------------------------------
__device__ __forceinline__ float coarse_key(float lo, float u) {
    float w  = 1.0f - u;                 // exact for u > 0.5 (Sterbenz)
    float ts = fmaf(0.5f * w, w, w);     // w + w^2/2
    float tl = -__logf(u);
    float t  = (u > 0.99609375f) ? ts : tl;
    return lo - __logf(t);
}

__device__ __forceinline__ double precise_key(float lo, float u) {
    return (double)lo - log(-log((double)u));
}

__device__ __forceinline__ void ins2(float k, int j,
                                     float& v1, int& i1,
                                     float& v2, int& i2) {
    bool p = k > v1;
    float dv = p ? v1 : k;
    int   di = p ? i1 : j;
    if (p) { v1 = k; i1 = j; }
    if (dv > v2) { v2 = dv; i2 = di; }
}

__device__ __forceinline__ void top2_insert(float w, int j,
                                            float& v1, int& i1,
                                            float& v2, int& i2) {
    if (w > v1 || (w == v1 && j < i1)) {
        v2 = v1; i2 = i1; v1 = w; i1 = j;
    } else if (w > v2 || (w == v2 && j < i2)) {
        v2 = w; i2 = j;
    }
}

// ---------------------------------------------------------------------------
// ONE launch: [psg blocks BB] [scan blocks NT*CH] [finish blocks NT].
// CTAs dispatch in ID order => all producers dispatched before consumers.
// __launch_bounds__(NTH, 8) caps regs at 32 (scan hot path fits; cold paths
// may spill — harmless).
// ---------------------------------------------------------------------------
__global__ void __launch_bounds__(NTH, 8)
fused_kernel(const float* __restrict__ logits,
             const float* __restrict__ gu,
             const float* __restrict__ W,
             const int*   __restrict__ rwrt,
             const int*   __restrict__ psg_in,
             float*       __restrict__ out) {
    const int tid = threadIdx.x;

    // ================= psg blocks =================
    if (blockIdx.x < BB) {
        __shared__ int s_r[LL];
        __shared__ int s_p[LL];
        const int b = blockIdx.x;
        if (tid >= 32) return;
        const int lane = tid;

        int cnt = 0;
#pragma unroll
        for (int k = 0; k < LL / 32; k++) {
            int l  = lane + 32 * k;
            int rv = rwrt[b * LL + l];
            s_r[l] = rv;
            s_p[l] = psg_in[b * LL + l];
            cnt += (rv == 1);
        }
        __syncwarp();
#pragma unroll
        for (int o = 16; o > 0; o >>= 1)
            cnt += __shfl_xor_sync(0xFFFFFFFFu, cnt, o);
        const int shift = cnt;

        int tr[LL / 32];
        int firstnz = LL;
#pragma unroll
        for (int k = 0; k < LL / 32; k++) {
            int l   = lane + 32 * k;
            int pos = ((l - shift) % LL + LL) % LL;
            int fm  = 1 - s_r[LL - 1 - pos];
            int psv = (pos == 0) ? 1 : s_p[pos - 1];
            int t   = fm * psv;
            tr[k] = t;
            if (t != 0) firstnz = min(firstnz, l);
        }
#pragma unroll
        for (int o = 16; o > 0; o >>= 1)
            firstnz = min(firstnz, __shfl_xor_sync(0xFFFFFFFFu, firstnz, o));
#pragma unroll
        for (int k = 0; k < LL / 32; k++) {
            int l = lane + 32 * k;
            g_ps[b * LL + l] = (l >= firstnz) ? tr[k] : -1;
        }
        __syncwarp();
        if (lane == 0) {
            __threadfence();
            g_psflag[b] = 1u;    // set-once; data identical on every replay
        }
        return;
    }

    // ================= finish blocks (grid tail) =================
    if (blockIdx.x >= BB + NBLK_SCAN) {
        const int t = blockIdx.x - (BB + NBLK_SCAN);   // 0..NT-1
        const int b = t / LL;
        __shared__ int s_res[2];

        if (tid == 0) {
            while (__ldcg(&g_cnt[t]) < (unsigned)CH) __nanosleep(64);
            while (__ldcg(&g_psflag[b]) == 0u)       __nanosleep(64);
            __threadfence();   // acquire
        }
        __syncthreads();

        if (tid < 32) {
            float v1 = -INFINITY, v2 = -INFINITY;
            int   i1 = 0,         i2 = 1;
            if (tid < CH) {
                int4 pr = __ldcg((int4*)&g_part[t * CH + tid]);
                v1 = __int_as_float(pr.x); i1 = pr.y;
                v2 = __int_as_float(pr.z); i2 = pr.w;
            }
#pragma unroll
            for (int off = 4; off > 0; off >>= 1) {
                float w1 = __shfl_xor_sync(0xFFFFFFFFu, v1, off);
                int   j1 = __shfl_xor_sync(0xFFFFFFFFu, i1, off);
                float w2 = __shfl_xor_sync(0xFFFFFFFFu, v2, off);
                int   j2 = __shfl_xor_sync(0xFFFFFFFFu, i2, off);
                top2_insert(w1, j1, v1, i1, v2, i2);
                top2_insert(w2, j2, v1, i1, v2, i2);
            }
            if (tid == 0) {
                int win = i1;
                if (v1 - v2 < 4e-3f) {
                    // near-tie (~0.4%): fp64 re-decide; coarse error <= 2.4e-4
                    double k1 = precise_key(logits[(size_t)t * VV + i1],
                                            gu[(size_t)t * VV + i1]);
                    double k2 = precise_key(logits[(size_t)t * VV + i2],
                                            gu[(size_t)t * VV + i2]);
                    if (k2 > k1 || (k2 == k1 && i2 < i1)) win = i2;
                }
                s_res[0] = (rwrt[t] != 0 && win < AVV) ? win : -1;
                s_res[1] = g_ps[t];
                g_cnt[t] = 0u;     // reset for next graph replay (sole consumer)
            }
        }
        __syncthreads();

        if (tid < ND4) {
            const int am = s_res[0];
            const int ps = s_res[1];
            const float4* W4 = (const float4*)W;
            float4 acc = make_float4(0.f, 0.f, 0.f, 0.f);
            if (am >= 0) acc = W4[(size_t)am * ND4 + tid];
            if (ps >= 0) {
                float4 wv = W4[(size_t)ps * ND4 + tid];
                acc.x += wv.x; acc.y += wv.y; acc.z += wv.z; acc.w += wv.w;
            }
            ((float4*)out)[(size_t)t * ND4 + tid] = acc;
        }
        return;
    }

    // ================= scan blocks =================
    const int blk = blockIdx.x - BB;
    const int t   = blk >> 2;
    const int c   = blk & 3;

    const float4* lg = (const float4*)(logits + (size_t)t * VV) + c * CV4;
    const float4* gg = (const float4*)(gu     + (size_t)t * VV) + c * CV4;
    const int jbase = c * CV4 * 4;

    float v1 = -INFINITY, v2 = -INFINITY;
    int   i1 = 0,         i2 = 1;

    // seed: one exact float4 per lane, warp-wide 2nd-max -> thr
    {
        float4 a = __ldcs(lg + tid);
        float4 g = __ldcs(gg + tid);
        int base = jbase + 4 * tid;
        ins2(coarse_key(a.x, g.x), base + 0, v1, i1, v2, i2);
        ins2(coarse_key(a.y, g.y), base + 1, v1, i1, v2, i2);
        ins2(coarse_key(a.z, g.z), base + 2, v1, i1, v2, i2);
        ins2(coarse_key(a.w, g.w), base + 3, v1, i1, v2, i2);
    }
    float sa = v1, sb = v2;
#pragma unroll
    for (int off = 16; off > 0; off >>= 1) {
        float oa = __shfl_xor_sync(0xFFFFFFFFu, sa, off);
        float ob = __shfl_xor_sync(0xFFFFFFFFu, sb, off);
        float hi  = fmaxf(sa, oa);
        float lo2 = fmaxf(fminf(sa, oa), fmaxf(sb, ob));
        sa = hi; sb = lo2;
    }

    const float CC  = 8.2629582e-8f;    // ln2 / 2^23
    const float CBE = 88.029703f;       // 127*ln2 + 1e-5 margin
    float thr2 = fmaxf(v2, sb) - CBE;

    // main loop: per-element UBs (independent FFMA), 3-FMAX tree, 1 FSETP.
#pragma unroll 2
    for (int i = tid + NTH; i < CV4; i += NTH) {
        float4 a = __ldcs(lg + i);
        float4 g = __ldcs(gg + i);
        float ub0 = fmaf(-CC, (float)__float_as_int(1.0f - g.x), a.x);
        float ub1 = fmaf(-CC, (float)__float_as_int(1.0f - g.y), a.y);
        float ub2 = fmaf(-CC, (float)__float_as_int(1.0f - g.z), a.z);
        float ub3 = fmaf(-CC, (float)__float_as_int(1.0f - g.w), a.w);
        float m = fmaxf(fmaxf(ub0, ub1), fmaxf(ub2, ub3));
        if (m > thr2) {
            int base = jbase + 4 * i;
            ins2(coarse_key(a.x, g.x), base + 0, v1, i1, v2, i2);
            ins2(coarse_key(a.y, g.y), base + 1, v1, i1, v2, i2);
            ins2(coarse_key(a.z, g.z), base + 2, v1, i1, v2, i2);
            ins2(coarse_key(a.w, g.w), base + 3, v1, i1, v2, i2);
            thr2 = fmaxf(thr2, v2 - CBE);
        }
    }

    // block top-2 reduction (index tie-break)
    __shared__ float s_v1[NTH]; __shared__ int s_i1[NTH];
    __shared__ float s_v2[NTH]; __shared__ int s_i2[NTH];
    s_v1[tid] = v1; s_i1[tid] = i1;
    s_v2[tid] = v2; s_i2[tid] = i2;
    __syncthreads();
    for (int s = NTH / 2; s > 0; s >>= 1) {
        if (tid < s) {
            float w1 = s_v1[tid + s], w2 = s_v2[tid + s];
            int   j1 = s_i1[tid + s], j2 = s_i2[tid + s];
            float a1 = s_v1[tid],     a2 = s_v2[tid];
            int   c1 = s_i1[tid],     c2 = s_i2[tid];
            top2_insert(w1, j1, a1, c1, a2, c2);
            top2_insert(w2, j2, a1, c1, a2, c2);
            s_v1[tid] = a1; s_i1[tid] = c1;
            s_v2[tid] = a2; s_i2[tid] = c2;
        }
        __syncthreads();
    }
    if (tid == 0) {
        g_part[blk] = make_int4(__float_as_int(s_v1[0]), s_i1[0],
                                __float_as_int(s_v2[0]), s_i2[0]);
        __threadfence();                       // release partial before count
        atomicAdd(&g_cnt[t], 1u);
    }
}

// ---------------------------------------------------------------------------
extern "C" void kernel_launch(void* const* d_in, const int* in_sizes, int n_in,
                              void* d_out, int out_size) {
    const float* logits = (const float*)d_in[0];
    const float* gu     = (const float*)d_in[1];
    const float* W      = (const float*)d_in[2];
    const int*   rwrt   = (const int*)d_in[3];
    const int*   psg    = (const int*)d_in[4];
    float* out = (float*)d_out;

    fused_kernel<<<GRID_TOTAL, NTH>>>(logits, gu, W, rwrt, psg, out);
}